// round 11
// baseline (speedup 1.0000x reference)
#include <cuda_runtime.h>
#include <cuda_fp16.h>
#include <cstdint>
#include <cstddef>

// ---------------------------------------------------------------------------
// BufferAttend1d (sm_100). B=8, Q=K=4096, DIN=256, d=64.
// Output: probs (8*4096*4096 f32) ++ read (8*4096*64 f32).
//
// All-fp16 operand path (f32 accumulate):
//  proj: x->g_Qh (fp16, pre-scaled log2e/8), buffer->g_Kh (fp16),
//        buffer->g_Vt (fp16, transposed [b*64+vd][seq]).
//  attn: q-tile 128 (256 thr, 8 warps), k-tile 64, cp.async double buffered.
//    QK fp16 m16n8k16 -> e = keep*exp2(l) -> E fp16 smem -> PV fp16 -> O f32.
//    E tile stored fp16 to g_E scratch (half the f32 traffic).
//    Tail: CTA streams its own strip g_E(fp16) -> probs(f32) * inv. This
//    replaces the 1.07GB f32 RMW rescale with 268r+537w one-shot expand.
// ---------------------------------------------------------------------------

#define SEQ   4096
#define NB    8
#define DIN   256
#define HD    64
#define NROWS (NB*SEQ)
#define PROBS_ELEMS (8LL*4096LL*4096LL)
#define KT2   64
#define NT2   (SEQ/KT2)    // 64

// attn smem byte offsets (fp16 tiles, row stride 144B = 72 halves)
#define Q_B   0              // 128 x 144                     = 18432
#define E_B   18432          // 128 x 144                     = 18432
#define K_B   36864          // 2 x (64 x 144)                = 18432
#define V_B   55296          // 2 x (64 x 144)                = 18432
#define KP_B  73728          // 2 x 256
#define RS_B  74240          // 128*2*4 = 1024
#define IV_B  75264          // 128*4   = 512
#define ATTN_SMEM 75776

__device__ uint16_t g_Qh[(size_t)NROWS*HD];
__device__ uint16_t g_Kh[(size_t)NROWS*HD];
__device__ uint16_t g_Vt[(size_t)NB*HD*SEQ];       // [b*64+vd][seq]
__device__ uint16_t g_E[(size_t)NB*SEQ*SEQ];       // fp16 unnormalized e
__device__ float    g_keep[NROWS];
__device__ int      g_mask_fmt;

__device__ __forceinline__ uint32_t f2tf(float x){uint32_t y;asm("cvt.rna.tf32.f32 %0, %1;":"=r"(y):"f"(x));return y;}
__device__ __forceinline__ float fexp2(float x){float y;asm("ex2.approx.f32 %0, %1;":"=f"(y):"f"(x));return y;}
__device__ __forceinline__ uint32_t smem_u32(const void* p){uint32_t a;asm("{ .reg .u64 t; cvta.to.shared.u64 t, %1; cvt.u32.u64 %0, t; }":"=r"(a):"l"(p));return a;}
__device__ __forceinline__ void cpa16(uint32_t s, const void* g){
    asm volatile("cp.async.cg.shared.global [%0], [%1], 16;"::"r"(s),"l"(g));
}
#define CP_COMMIT() asm volatile("cp.async.commit_group;" ::: "memory")
#define CP_WAIT1()  asm volatile("cp.async.wait_group 1;" ::: "memory")
#define CP_WAIT0()  asm volatile("cp.async.wait_group 0;" ::: "memory")

__device__ __forceinline__ void mma8(float* c, const uint32_t* a, const uint32_t* b){
    asm volatile("mma.sync.aligned.m16n8k8.row.col.f32.tf32.tf32.f32 "
        "{%0,%1,%2,%3}, {%4,%5,%6,%7}, {%8,%9}, {%0,%1,%2,%3};\n"
        : "+f"(c[0]),"+f"(c[1]),"+f"(c[2]),"+f"(c[3])
        : "r"(a[0]),"r"(a[1]),"r"(a[2]),"r"(a[3]),"r"(b[0]),"r"(b[1]));
}
__device__ __forceinline__ void mma16h(float* c, const uint32_t* a, const uint32_t* b){
    asm volatile("mma.sync.aligned.m16n8k16.row.col.f32.f16.f16.f32 "
        "{%0,%1,%2,%3}, {%4,%5,%6,%7}, {%8,%9}, {%0,%1,%2,%3};\n"
        : "+f"(c[0]),"+f"(c[1]),"+f"(c[2]),"+f"(c[3])
        : "r"(a[0]),"r"(a[1]),"r"(a[2]),"r"(a[3]),"r"(b[0]),"r"(b[1]));
}
__device__ __forceinline__ void zero4(float a[2][4][4]){
#pragma unroll
    for(int i=0;i<2;i++)
#pragma unroll
        for(int j=0;j<4;j++)
#pragma unroll
            for(int k=0;k<4;k++) a[i][j][k]=0.f;
}

// ---------------- mask ----------------
__global__ void mask_detect_kernel(const uint32_t* __restrict__ mw){
    __shared__ int iok_s, fok_s;
    if(threadIdx.x==0){iok_s=1;fok_s=1;}
    __syncthreads();
    int iok=1, fok=1;
    for(int i=threadIdx.x;i<NROWS/4;i+=blockDim.x){
        uint32_t v=mw[i];
        if(v!=0u&&v!=1u) iok=0;
        if(v!=0u&&v!=0x3F800000u) fok=0;
    }
    if(!iok) atomicExch(&iok_s,0);
    if(!fok) atomicExch(&fok_s,0);
    __syncthreads();
    if(threadIdx.x==0) g_mask_fmt = iok_s?1:(fok_s?2:0);
}
__global__ void mask_decode_kernel(const void* __restrict__ mp){
    int i=blockIdx.x*blockDim.x+threadIdx.x;
    if(i>=NROWS) return;
    int f=g_mask_fmt, m;
    if(f==1) m=((const int*)mp)[i]!=0;
    else if(f==2) m=((const float*)mp)[i]!=0.0f;
    else m=((const unsigned char*)mp)[i]!=0;
    g_keep[i]= m?0.0f:1.0f;
}

// ---------------- projection (tf32 mma, fp16 outputs) ----------------
#define PROJ_SMEM_BYTES ((128*68+64*68)*4)
__global__ __launch_bounds__(256) void proj_kernel(
    const float* __restrict__ x, const float* __restrict__ buf,
    const float* __restrict__ Wk, const float* __restrict__ bk,
    const float* __restrict__ Wv, const float* __restrict__ bv)
{
    extern __shared__ float sm[];
    float* As=sm; float* Ws=sm+128*68;
    const int tid=threadIdx.x, lane=tid&31, wid=tid>>5;
    const int g=lane>>2, t=lane&3, wm=wid&3, wn=wid>>2;
    const bool isx = blockIdx.x<256;
    const int row0=(blockIdx.x&255)*128;
    const float* in = isx?x:buf;
    const int nsweep = isx?1:2;
    const float osc = isx ? 0.125f*1.4426950408889634f : 1.0f;

    for(int sw=0; sw<nsweep; sw++){
        const float* W=(sw==0)?Wk:Wv;
        const float* bias=(sw==0)?bk:bv;
        const int isV = (!isx) && (sw==1);
        float acc[2][4][4];
        zero4(acc);
        for(int kc=0;kc<4;kc++){
            __syncthreads();
            for(int i=tid;i<128*16;i+=256){
                int r=i>>4,c=(i&15)*4;
                *(float4*)&As[r*68+c] = *(const float4*)&in[(size_t)(row0+r)*DIN+kc*64+c];
            }
            for(int i=tid;i<64*16;i+=256){
                int r=i>>4,c=(i&15)*4;
                *(float4*)&Ws[r*68+c] = *(const float4*)&W[(size_t)r*DIN+kc*64+c];
            }
            __syncthreads();
#pragma unroll
            for(int ks=0;ks<8;ks++){
                const int k0=ks*8;
                uint32_t a[2][4], bb[4][2];
#pragma unroll
                for(int mi=0;mi<2;mi++){
                    const float* ap=As+(wm*32+mi*16+g)*68+k0+t;
                    a[mi][0]=f2tf(ap[0]); a[mi][1]=f2tf(ap[8*68]);
                    a[mi][2]=f2tf(ap[4]); a[mi][3]=f2tf(ap[8*68+4]);
                }
#pragma unroll
                for(int ni=0;ni<4;ni++){
                    const float* bp=Ws+(wn*32+ni*8+g)*68+k0+t;
                    bb[ni][0]=f2tf(bp[0]); bb[ni][1]=f2tf(bp[4]);
                }
#pragma unroll
                for(int mi=0;mi<2;mi++)
#pragma unroll
                    for(int ni=0;ni<4;ni++) mma8(acc[mi][ni],a[mi],bb[ni]);
            }
        }
#pragma unroll
        for(int mi=0;mi<2;mi++)
#pragma unroll
            for(int ni=0;ni<4;ni++){
                int r=row0+wm*32+mi*16+g, col=wn*32+ni*8+t*2;
                float b0=__ldg(&bias[col]), b1=__ldg(&bias[col+1]);
                float v00=acc[mi][ni][0]+b0, v01=acc[mi][ni][1]+b1;
                float v10=acc[mi][ni][2]+b0, v11=acc[mi][ni][3]+b1;
                if(isV){
                    int b_  = r>>12,      s0 = r&4095;
                    int b2  = (r+8)>>12,  s1 = (r+8)&4095;
                    g_Vt[((size_t)(b_*64+col  )<<12)+s0]=__half_as_ushort(__float2half_rn(v00));
                    g_Vt[((size_t)(b_*64+col+1)<<12)+s0]=__half_as_ushort(__float2half_rn(v01));
                    g_Vt[((size_t)(b2*64+col  )<<12)+s1]=__half_as_ushort(__float2half_rn(v10));
                    g_Vt[((size_t)(b2*64+col+1)<<12)+s1]=__half_as_ushort(__float2half_rn(v11));
                } else {
                    uint16_t* out = isx ? g_Qh : g_Kh;
                    __half2 h0=__floats2half2_rn(v00*osc, v01*osc);
                    __half2 h1=__floats2half2_rn(v10*osc, v11*osc);
                    *(__half2*)(out+(size_t)r*HD+col)     = h0;
                    *(__half2*)(out+(size_t)(r+8)*HD+col) = h1;
                }
            }
    }
}

// ---------------- attention ----------------
__device__ __forceinline__ void stage_cp(uint32_t sb, int bi, int krg, int b, int k0l, int tid){
    const uint32_t kd = sb + K_B + bi*9216;
#pragma unroll
    for(int j=0;j<2;j++){
        int idx = tid + j*256;             // 0..511
        int row = idx>>3, ch = idx&7;
        cpa16(kd + (uint32_t)row*144 + (uint32_t)ch*16,
              (const char*)(g_Kh + (size_t)(krg+row)*HD) + ch*16);
    }
    const uint32_t vd = sb + V_B + bi*9216;
#pragma unroll
    for(int j=0;j<2;j++){
        int idx = tid + j*256;
        int row = idx>>3, ch = idx&7;
        cpa16(vd + (uint32_t)row*144 + (uint32_t)ch*16,
              (const char*)(g_Vt + ((size_t)(b*64+row)<<12) + k0l) + ch*16);
    }
    if(tid<16) cpa16(sb+KP_B+bi*256+tid*16, (const char*)(g_keep+krg)+tid*16);
}

__global__ __launch_bounds__(256,2) void attn_kernel(float* __restrict__ outp)
{
    extern __shared__ char smc[];
    const uint32_t sb = smem_u32(smc);
    float* rs2 =(float*)(smc+RS_B);
    float* invs=(float*)(smc+IV_B);

    const int tid=threadIdx.x, lane=tid&31, wid=tid>>5;
    const int g=lane>>2, t=lane&3;
    const int wm=wid&3, wn=wid>>2;
    const int b=blockIdx.x>>5, q0=(blockIdx.x&31)*128;
    const int kb0=b<<12;

    // stage Q tile (fp16, pre-scaled) via cp.async
#pragma unroll
    for(int j=0;j<4;j++){
        int idx = tid + j*256;             // 0..1023
        int row = idx>>3, ch = idx&7;
        cpa16(sb+Q_B + (uint32_t)row*144 + (uint32_t)ch*16,
              (const char*)(g_Qh + (size_t)(kb0+q0+row)*HD) + ch*16);
    }
    CP_COMMIT();
    stage_cp(sb, 0, kb0, b, 0, tid);
    CP_COMMIT();

    float o[2][4][4];
    zero4(o);
    float rsum[2][2]={{0.f,0.f},{0.f,0.f}};

    for(int i=0;i<NT2;i++){
        const int cur=i&1;
        __syncthreads();                       // prior readers of buf(cur^1), E done
        if(i+1<NT2){
            stage_cp(sb, cur^1, kb0+(i+1)*KT2, b, (i+1)*KT2, tid);
            CP_COMMIT();
            CP_WAIT1();
        } else {
            CP_WAIT0();
        }
        __syncthreads();                       // Q (iter0) + buf(cur) visible

        // ---- QK (fp16 m16n8k16): lfr = Q @ K^T
        float lfr[2][4][4];
        zero4(lfr);
#pragma unroll
        for(int kc=0;kc<4;kc++){
            const int k0=kc*16;
            uint32_t a[2][4], bb[4][2];
#pragma unroll
            for(int mi=0;mi<2;mi++){
                const char* ap = smc+Q_B + ((size_t)(wm*32+mi*16+g)*72 + k0 + 2*t)*2;
                a[mi][0]=*(const uint32_t*)(ap);
                a[mi][1]=*(const uint32_t*)(ap + 8*144);
                a[mi][2]=*(const uint32_t*)(ap + 16);
                a[mi][3]=*(const uint32_t*)(ap + 8*144+16);
            }
#pragma unroll
            for(int ni=0;ni<4;ni++){
                const char* bp = smc+K_B+cur*9216 + ((size_t)(wn*32+ni*8+g)*72 + k0 + 2*t)*2;
                bb[ni][0]=*(const uint32_t*)(bp);
                bb[ni][1]=*(const uint32_t*)(bp + 16);
            }
#pragma unroll
            for(int mi=0;mi<2;mi++)
#pragma unroll
                for(int ni=0;ni<4;ni++) mma16h(lfr[mi][ni],a[mi],bb[ni]);
        }

        // ---- epilogue: e = keep * exp2(l) -> E fp16; register rowsum
        const float* kp=(const float*)(smc+KP_B+cur*256);
#pragma unroll
        for(int mi=0;mi<2;mi++){
            const int r=wm*32+mi*16+g;
#pragma unroll
            for(int ni=0;ni<4;ni++){
                const int col=wn*32+ni*8+t*2;
                const float k0v=kp[col], k1v=kp[col+1];
                float e00=k0v*fexp2(lfr[mi][ni][0]);
                float e01=k1v*fexp2(lfr[mi][ni][1]);
                float e10=k0v*fexp2(lfr[mi][ni][2]);
                float e11=k1v*fexp2(lfr[mi][ni][3]);
                *(__half2*)(smc+E_B+((size_t)r*72+col)*2)     = __floats2half2_rn(e00,e01);
                *(__half2*)(smc+E_B+((size_t)(r+8)*72+col)*2) = __floats2half2_rn(e10,e11);
                rsum[mi][0]+=e00+e01;
                rsum[mi][1]+=e10+e11;
            }
        }
        __syncthreads();                       // E visible

        // ---- PV (fp16): O += E @ Vt^T
#pragma unroll
        for(int kc=0;kc<4;kc++){
            const int k0=kc*16;
            uint32_t a[2][4], bb[4][2];
#pragma unroll
            for(int mi=0;mi<2;mi++){
                const char* ap = smc+E_B + ((size_t)(wm*32+mi*16+g)*72 + k0 + 2*t)*2;
                a[mi][0]=*(const uint32_t*)(ap);
                a[mi][1]=*(const uint32_t*)(ap + 8*144);
                a[mi][2]=*(const uint32_t*)(ap + 16);
                a[mi][3]=*(const uint32_t*)(ap + 8*144+16);
            }
#pragma unroll
            for(int ni=0;ni<4;ni++){
                const char* bp = smc+V_B+cur*9216 + ((size_t)(wn*32+ni*8+g)*72 + k0 + 2*t)*2;
                bb[ni][0]=*(const uint32_t*)(bp);
                bb[ni][1]=*(const uint32_t*)(bp + 16);
            }
#pragma unroll
            for(int mi=0;mi<2;mi++)
#pragma unroll
                for(int ni=0;ni<4;ni++) mma16h(o[mi][ni],a[mi],bb[ni]);
        }

        // ---- store E tile as fp16 to g_E scratch (coalesced, 16KB/tile)
#pragma unroll
        for(int j=0;j<4;j++){
            int idx = tid + j*256;             // 0..1023
            int row = idx>>3, ch = idx&7;      // 128 rows x 8 chunks of 16B
            uint4 w = *(const uint4*)(smc+E_B+(size_t)row*144+ch*16);
            *(uint4*)(g_E + ((size_t)(kb0+q0+row)<<12) + (size_t)i*KT2 + ch*8) = w;
        }
    }

    // ---- deterministic rowsum reduce -> inv
#pragma unroll
    for(int mi=0;mi<2;mi++)
#pragma unroll
        for(int h=0;h<2;h++){
            float v=rsum[mi][h];
            v+=__shfl_xor_sync(0xffffffffu,v,1);
            v+=__shfl_xor_sync(0xffffffffu,v,2);
            if(t==0) rs2[(wm*32+mi*16+h*8+g)*2+wn]=v;
        }
    __syncthreads();
    if(tid<128) invs[tid]=1.0f/(rs2[2*tid]+rs2[2*tid+1]);
    __syncthreads();

    // ---- read output
    {
        float* rout = outp + PROBS_ELEMS;
#pragma unroll
        for(int mi=0;mi<2;mi++){
            const int r=wm*32+mi*16+g;
            const float i0=invs[r], i1=invs[r+8];
#pragma unroll
            for(int ni=0;ni<4;ni++){
                const int col=wn*32+ni*8+t*2;
                size_t o0=(size_t)(kb0+q0+r)*HD+col;
                size_t o1=(size_t)(kb0+q0+r+8)*HD+col;
                rout[o0]  =o[mi][ni][0]*i0;
                rout[o0+1]=o[mi][ni][1]*i0;
                rout[o1]  =o[mi][ni][2]*i1;
                rout[o1+1]=o[mi][ni][3]*i1;
            }
        }
    }

    // ---- normalize-expand: g_E strip (fp16) -> probs (f32) * inv
    for(int rr=0; rr<16; rr++){
        const int row = wid*16 + rr;
        const float inv = invs[row];
        const uint4* src = (const uint4*)(g_E + ((size_t)(kb0+q0+row)<<12));
        float4* dst = (float4*)(outp + (size_t)(kb0+q0+row)*SEQ);
#pragma unroll 4
        for(int j=0;j<16;j++){
            uint4 w = src[lane + j*32];
            const __half2* h=(const __half2*)&w;
            float2 f0=__half22float2(h[0]), f1=__half22float2(h[1]);
            float2 f2=__half22float2(h[2]), f3=__half22float2(h[3]);
            float4 p0, p1;
            p0.x=f0.x*inv; p0.y=f0.y*inv; p0.z=f1.x*inv; p0.w=f1.y*inv;
            p1.x=f2.x*inv; p1.y=f2.y*inv; p1.z=f3.x*inv; p1.w=f3.y*inv;
            dst[(lane+j*32)*2]   = p0;
            dst[(lane+j*32)*2+1] = p1;
        }
    }
}

// ---------------------------------------------------------------------------
extern "C" void kernel_launch(void* const* d_in, const int* in_sizes, int n_in,
                              void* d_out, int out_size) {
    const float* x  =(const float*)d_in[0];
    const float* buf=(const float*)d_in[1];
    const void*  msk=d_in[2];
    const float* Wk =(const float*)d_in[3];
    const float* bk =(const float*)d_in[4];
    const float* Wv =(const float*)d_in[5];
    const float* bv =(const float*)d_in[6];
    float* outp=(float*)d_out;

    cudaFuncSetAttribute(proj_kernel, cudaFuncAttributeMaxDynamicSharedMemorySize, PROJ_SMEM_BYTES);
    cudaFuncSetAttribute(attn_kernel, cudaFuncAttributeMaxDynamicSharedMemorySize, ATTN_SMEM);

    proj_kernel<<<512, 256, PROJ_SMEM_BYTES>>>(x, buf, Wk, bk, Wv, bv);
    mask_detect_kernel<<<1, 256>>>((const uint32_t*)msk);
    mask_decode_kernel<<<NROWS/256, 256>>>(msk);
    attn_kernel<<<256, 256, ATTN_SMEM>>>(outp);
}

// round 14
// speedup vs baseline: 1.0139x; 1.0139x over previous
#include <cuda_runtime.h>
#include <cuda_fp16.h>
#include <cstdint>
#include <cstddef>

// ---------------------------------------------------------------------------
// BufferAttend1d (sm_100). B=8, Q=K=4096, DIN=256, d=64.
// Output: probs (8*4096*4096 f32) ++ read (8*4096*64 f32).
//
// Flash-style register-resident-P layout:
//  Each warp owns 16 q-rows x all 64 keys. QK output fragments are repacked
//  in-register into PV A-fragments (no E smem round trip, no E barrier).
//  3-stage cp.async pipeline on K/V. Rowsum is warp-local (quad shuffle).
//  E tile -> g_E fp16 scratch (warp-private smem strip, __syncwarp only);
//  tail expands g_E -> normalized f32 probs per warp.
// ---------------------------------------------------------------------------

#define SEQ   4096
#define NB    8
#define DIN   256
#define HD    64
#define NROWS (NB*SEQ)
#define PROBS_ELEMS (8LL*4096LL*4096LL)
#define KT2   64
#define NT2   (SEQ/KT2)    // 64

// attn smem byte offsets
#define E_B   0              // 128 x 144B                    = 18432
#define K_B   18432          // 3 x (64 x 144B)               = 27648
#define V_B   46080          // 3 x (64 x 144B)               = 27648
#define KP_B  73728          // 3 x 256
#define IV_B  74496          // 128*4 = 512
#define ATTN_SMEM 75008

__device__ uint16_t g_Qh[(size_t)NROWS*HD];
__device__ uint16_t g_Kh[(size_t)NROWS*HD];
__device__ uint16_t g_Vt[(size_t)NB*HD*SEQ];       // [b*64+vd][seq]
__device__ uint16_t g_E[(size_t)NB*SEQ*SEQ];       // fp16 unnormalized e
__device__ float    g_keep[NROWS];
__device__ int      g_mask_fmt;

__device__ __forceinline__ uint32_t f2tf(float x){uint32_t y;asm("cvt.rna.tf32.f32 %0, %1;":"=r"(y):"f"(x));return y;}
__device__ __forceinline__ float fexp2(float x){float y;asm("ex2.approx.f32 %0, %1;":"=f"(y):"f"(x));return y;}
__device__ __forceinline__ uint32_t smem_u32(const void* p){uint32_t a;asm("{ .reg .u64 t; cvta.to.shared.u64 t, %1; cvt.u32.u64 %0, t; }":"=r"(a):"l"(p));return a;}
__device__ __forceinline__ void cpa16(uint32_t s, const void* g){
    asm volatile("cp.async.cg.shared.global [%0], [%1], 16;"::"r"(s),"l"(g));
}
#define CP_COMMIT() asm volatile("cp.async.commit_group;" ::: "memory")
#define CP_WAIT2()  asm volatile("cp.async.wait_group 2;" ::: "memory")
#define CP_WAIT1()  asm volatile("cp.async.wait_group 1;" ::: "memory")
#define CP_WAIT0()  asm volatile("cp.async.wait_group 0;" ::: "memory")

__device__ __forceinline__ void mma8(float* c, const uint32_t* a, const uint32_t* b){
    asm volatile("mma.sync.aligned.m16n8k8.row.col.f32.tf32.tf32.f32 "
        "{%0,%1,%2,%3}, {%4,%5,%6,%7}, {%8,%9}, {%0,%1,%2,%3};\n"
        : "+f"(c[0]),"+f"(c[1]),"+f"(c[2]),"+f"(c[3])
        : "r"(a[0]),"r"(a[1]),"r"(a[2]),"r"(a[3]),"r"(b[0]),"r"(b[1]));
}
__device__ __forceinline__ void mma16h(float* c, const uint32_t* a, uint32_t b0, uint32_t b1){
    asm volatile("mma.sync.aligned.m16n8k16.row.col.f32.f16.f16.f32 "
        "{%0,%1,%2,%3}, {%4,%5,%6,%7}, {%8,%9}, {%0,%1,%2,%3};\n"
        : "+f"(c[0]),"+f"(c[1]),"+f"(c[2]),"+f"(c[3])
        : "r"(a[0]),"r"(a[1]),"r"(a[2]),"r"(a[3]),"r"(b0),"r"(b1));
}

// ---------------- mask ----------------
__global__ void mask_detect_kernel(const uint32_t* __restrict__ mw){
    __shared__ int iok_s, fok_s;
    if(threadIdx.x==0){iok_s=1;fok_s=1;}
    __syncthreads();
    int iok=1, fok=1;
    for(int i=threadIdx.x;i<NROWS/4;i+=blockDim.x){
        uint32_t v=mw[i];
        if(v!=0u&&v!=1u) iok=0;
        if(v!=0u&&v!=0x3F800000u) fok=0;
    }
    if(!iok) atomicExch(&iok_s,0);
    if(!fok) atomicExch(&fok_s,0);
    __syncthreads();
    if(threadIdx.x==0) g_mask_fmt = iok_s?1:(fok_s?2:0);
}
__global__ void mask_decode_kernel(const void* __restrict__ mp){
    int i=blockIdx.x*blockDim.x+threadIdx.x;
    if(i>=NROWS) return;
    int f=g_mask_fmt, m;
    if(f==1) m=((const int*)mp)[i]!=0;
    else if(f==2) m=((const float*)mp)[i]!=0.0f;
    else m=((const unsigned char*)mp)[i]!=0;
    g_keep[i]= m?0.0f:1.0f;
}

// ---------------- projection (tf32 mma, fp16 outputs) ----------------
#define PROJ_SMEM_BYTES ((128*68+64*68)*4)
__global__ __launch_bounds__(256) void proj_kernel(
    const float* __restrict__ x, const float* __restrict__ buf,
    const float* __restrict__ Wk, const float* __restrict__ bk,
    const float* __restrict__ Wv, const float* __restrict__ bv)
{
    extern __shared__ float sm[];
    float* As=sm; float* Ws=sm+128*68;
    const int tid=threadIdx.x, lane=tid&31, wid=tid>>5;
    const int g=lane>>2, t=lane&3, wm=wid&3, wn=wid>>2;
    const bool isx = blockIdx.x<256;
    const int row0=(blockIdx.x&255)*128;
    const float* in = isx?x:buf;
    const int nsweep = isx?1:2;
    const float osc = isx ? 0.125f*1.4426950408889634f : 1.0f;

    for(int sw=0; sw<nsweep; sw++){
        const float* W=(sw==0)?Wk:Wv;
        const float* bias=(sw==0)?bk:bv;
        const int isV = (!isx) && (sw==1);
        float acc[2][4][4];
#pragma unroll
        for(int i=0;i<2;i++)
#pragma unroll
            for(int j=0;j<4;j++)
#pragma unroll
                for(int k=0;k<4;k++) acc[i][j][k]=0.f;
        for(int kc=0;kc<4;kc++){
            __syncthreads();
            for(int i=tid;i<128*16;i+=256){
                int r=i>>4,c=(i&15)*4;
                *(float4*)&As[r*68+c] = *(const float4*)&in[(size_t)(row0+r)*DIN+kc*64+c];
            }
            for(int i=tid;i<64*16;i+=256){
                int r=i>>4,c=(i&15)*4;
                *(float4*)&Ws[r*68+c] = *(const float4*)&W[(size_t)r*DIN+kc*64+c];
            }
            __syncthreads();
#pragma unroll
            for(int ks=0;ks<8;ks++){
                const int k0=ks*8;
                uint32_t a[2][4], bb[4][2];
#pragma unroll
                for(int mi=0;mi<2;mi++){
                    const float* ap=As+(wm*32+mi*16+g)*68+k0+t;
                    a[mi][0]=f2tf(ap[0]); a[mi][1]=f2tf(ap[8*68]);
                    a[mi][2]=f2tf(ap[4]); a[mi][3]=f2tf(ap[8*68+4]);
                }
#pragma unroll
                for(int ni=0;ni<4;ni++){
                    const float* bp=Ws+(wn*32+ni*8+g)*68+k0+t;
                    bb[ni][0]=f2tf(bp[0]); bb[ni][1]=f2tf(bp[4]);
                }
#pragma unroll
                for(int mi=0;mi<2;mi++)
#pragma unroll
                    for(int ni=0;ni<4;ni++) mma8(acc[mi][ni],a[mi],bb[ni]);
            }
        }
#pragma unroll
        for(int mi=0;mi<2;mi++)
#pragma unroll
            for(int ni=0;ni<4;ni++){
                int r=row0+wm*32+mi*16+g, col=wn*32+ni*8+t*2;
                float b0=__ldg(&bias[col]), b1=__ldg(&bias[col+1]);
                float v00=acc[mi][ni][0]+b0, v01=acc[mi][ni][1]+b1;
                float v10=acc[mi][ni][2]+b0, v11=acc[mi][ni][3]+b1;
                if(isV){
                    int b_  = r>>12,      s0 = r&4095;
                    int b2  = (r+8)>>12,  s1 = (r+8)&4095;
                    g_Vt[((size_t)(b_*64+col  )<<12)+s0]=__half_as_ushort(__float2half_rn(v00));
                    g_Vt[((size_t)(b_*64+col+1)<<12)+s0]=__half_as_ushort(__float2half_rn(v01));
                    g_Vt[((size_t)(b2*64+col  )<<12)+s1]=__half_as_ushort(__float2half_rn(v10));
                    g_Vt[((size_t)(b2*64+col+1)<<12)+s1]=__half_as_ushort(__float2half_rn(v11));
                } else {
                    uint16_t* out = isx ? g_Qh : g_Kh;
                    __half2 h0=__floats2half2_rn(v00*osc, v01*osc);
                    __half2 h1=__floats2half2_rn(v10*osc, v11*osc);
                    *(__half2*)(out+(size_t)r*HD+col)     = h0;
                    *(__half2*)(out+(size_t)(r+8)*HD+col) = h1;
                }
            }
    }
}

// ---------------- attention ----------------
__device__ __forceinline__ void stage_cp(uint32_t sb, int bi, int krg, int b, int k0l, int tid){
    const uint32_t kd = sb + K_B + bi*9216;
#pragma unroll
    for(int j=0;j<2;j++){
        int idx = tid + j*256;             // 0..511
        int row = idx>>3, ch = idx&7;
        cpa16(kd + (uint32_t)row*144 + (uint32_t)ch*16,
              (const char*)(g_Kh + (size_t)(krg+row)*HD) + ch*16);
    }
    const uint32_t vd = sb + V_B + bi*9216;
#pragma unroll
    for(int j=0;j<2;j++){
        int idx = tid + j*256;
        int row = idx>>3, ch = idx&7;
        cpa16(vd + (uint32_t)row*144 + (uint32_t)ch*16,
              (const char*)(g_Vt + ((size_t)(b*64+row)<<12) + k0l) + ch*16);
    }
    if(tid<16) cpa16(sb+KP_B+bi*256+tid*16, (const char*)(g_keep+krg)+tid*16);
}

__global__ __launch_bounds__(256,2) void attn_kernel(float* __restrict__ outp)
{
    extern __shared__ char smc[];
    const uint32_t sb = smem_u32(smc);
    float* invs=(float*)(smc+IV_B);

    const int tid=threadIdx.x, lane=tid&31, wid=tid>>5;
    const int g=lane>>2, t=lane&3;
    const int b=blockIdx.x>>5, q0=(blockIdx.x&31)*128;
    const int kb0=b<<12;
    const int row0 = kb0 + q0 + wid*16;    // this warp's global q-row base

    // ---- Q fragments: warp's 16 rows x full k=64, registers, loaded once
    uint32_t qa[4][4];
#pragma unroll
    for(int kc=0;kc<4;kc++){
        qa[kc][0]=*(const uint32_t*)&g_Qh[(size_t)(row0+g  )*HD + kc*16+2*t];
        qa[kc][1]=*(const uint32_t*)&g_Qh[(size_t)(row0+8+g)*HD + kc*16+2*t];
        qa[kc][2]=*(const uint32_t*)&g_Qh[(size_t)(row0+g  )*HD + kc*16+8+2*t];
        qa[kc][3]=*(const uint32_t*)&g_Qh[(size_t)(row0+8+g)*HD + kc*16+8+2*t];
    }

    // ---- prologue: stage tiles 0 and 1
    stage_cp(sb, 0, kb0,      b, 0,   tid); CP_COMMIT();
    stage_cp(sb, 1, kb0+KT2,  b, KT2, tid); CP_COMMIT();

    float o[8][4];
#pragma unroll
    for(int nj=0;nj<8;nj++)
#pragma unroll
        for(int k=0;k<4;k++) o[nj][k]=0.f;
    float rs0=0.f, rs1=0.f;

    char* eb = smc + E_B;   // warp-private strip rows wid*16..+15 (stride 144B)

    for(int i=0;i<NT2;i++){
        const int cur = i%3;
        __syncthreads();                   // readers of buf (i-1)%3 done
        if(i+2<NT2){
            stage_cp(sb, (i+2)%3, kb0+(i+2)*KT2, b, (i+2)*KT2, tid);
            CP_COMMIT();
            CP_WAIT2();                    // tile i guaranteed landed
        } else if(i+1<NT2){ CP_WAIT1(); } else { CP_WAIT0(); }
        __syncthreads();                   // all staging visible

        // ---- QK: lfr[ni] = Q(16 rows) @ K^T (full 64 keys)
        const char* Kbase = smc + K_B + cur*9216;
        float lfr[8][4];
#pragma unroll
        for(int nj=0;nj<8;nj++)
#pragma unroll
            for(int k=0;k<4;k++) lfr[nj][k]=0.f;
#pragma unroll
        for(int kc=0;kc<4;kc++){
#pragma unroll
            for(int ni=0;ni<8;ni++){
                const char* bp = Kbase + ((size_t)(ni*8+g)*72 + kc*16 + 2*t)*2;
                mma16h(lfr[ni], qa[kc], *(const uint32_t*)bp, *(const uint32_t*)(bp+16));
            }
        }

        // ---- epilogue: e = keep*exp2(l); pack PV A-frags; smem strip; rowsum
        const float* kp=(const float*)(smc+KP_B+cur*256);
        uint32_t ea[4][4];
#pragma unroll
        for(int ni=0;ni<8;ni++){
            const int col = ni*8 + 2*t;
            const float k0v=kp[col], k1v=kp[col+1];
            float e00=k0v*fexp2(lfr[ni][0]);
            float e01=k1v*fexp2(lfr[ni][1]);
            float e10=k0v*fexp2(lfr[ni][2]);
            float e11=k1v*fexp2(lfr[ni][3]);
            __half2 h0=__floats2half2_rn(e00,e01);
            __half2 h1=__floats2half2_rn(e10,e11);
            *(__half2*)(eb + ((size_t)(wid*16+g  )*72 + col)*2) = h0;
            *(__half2*)(eb + ((size_t)(wid*16+8+g)*72 + col)*2) = h1;
            ea[ni>>1][(ni&1)*2+0] = *(uint32_t*)&h0;
            ea[ni>>1][(ni&1)*2+1] = *(uint32_t*)&h1;
            rs0 += e00+e01;
            rs1 += e10+e11;
        }
        __syncwarp();

        // ---- PV: O += E(regs) @ Vt^T(smem)
        const char* Vbase = smc + V_B + cur*9216;
#pragma unroll
        for(int kc=0;kc<4;kc++){
#pragma unroll
            for(int nj=0;nj<8;nj++){
                const char* bp = Vbase + ((size_t)(nj*8+g)*72 + kc*16 + 2*t)*2;
                mma16h(o[nj], ea[kc], *(const uint32_t*)bp, *(const uint32_t*)(bp+16));
            }
        }

        // ---- e store to g_E scratch: warp-private rows, fully coalesced
#pragma unroll
        for(int ps=0;ps<4;ps++){
            int u = lane + ps*32;          // 0..127 = 16 rows x 8 chunks
            int row = u>>3, ch = u&7;
            uint4 w = *(const uint4*)(eb + ((size_t)(wid*16+row)*72 + ch*8)*2);
            *(uint4*)(g_E + ((size_t)(row0+row)<<12) + (size_t)i*KT2 + ch*8) = w;
        }
        __syncwarp();
    }

    // ---- warp-local rowsum reduce (quad shuffle) -> inv
    rs0 += __shfl_xor_sync(0xffffffffu, rs0, 1);
    rs0 += __shfl_xor_sync(0xffffffffu, rs0, 2);
    rs1 += __shfl_xor_sync(0xffffffffu, rs1, 1);
    rs1 += __shfl_xor_sync(0xffffffffu, rs1, 2);
    const float inv0 = 1.0f/rs0;
    const float inv1 = 1.0f/rs1;
    if(t==0){
        invs[wid*16+g]   = inv0;
        invs[wid*16+8+g] = inv1;
    }
    __syncwarp();

    // ---- read output (registers, warp-local)
    {
        float* rout = outp + PROBS_ELEMS;
#pragma unroll
        for(int nj=0;nj<8;nj++){
            const int col = nj*8 + 2*t;
            size_t o0=(size_t)(row0+g  )*HD+col;
            size_t o1=(size_t)(row0+8+g)*HD+col;
            rout[o0]  =o[nj][0]*inv0;
            rout[o0+1]=o[nj][1]*inv0;
            rout[o1]  =o[nj][2]*inv1;
            rout[o1+1]=o[nj][3]*inv1;
        }
    }

    // ---- normalize-expand: warp's own rows, g_E(fp16) -> probs(f32)*inv
    for(int rr=0; rr<16; rr++){
        const int row = wid*16 + rr;
        const float inv = invs[row];
        const uint4* src = (const uint4*)(g_E + ((size_t)(kb0+q0+row)<<12));
        float4* dst = (float4*)(outp + (size_t)(kb0+q0+row)*SEQ);
#pragma unroll 4
        for(int j=0;j<16;j++){
            uint4 w = src[lane + j*32];
            const __half2* h=(const __half2*)&w;
            float2 f0=__half22float2(h[0]), f1=__half22float2(h[1]);
            float2 f2=__half22float2(h[2]), f3=__half22float2(h[3]);
            float4 p0, p1;
            p0.x=f0.x*inv; p0.y=f0.y*inv; p0.z=f1.x*inv; p0.w=f1.y*inv;
            p1.x=f2.x*inv; p1.y=f2.y*inv; p1.z=f3.x*inv; p1.w=f3.y*inv;
            dst[(lane+j*32)*2]   = p0;
            dst[(lane+j*32)*2+1] = p1;
        }
    }
}

// ---------------------------------------------------------------------------
extern "C" void kernel_launch(void* const* d_in, const int* in_sizes, int n_in,
                              void* d_out, int out_size) {
    const float* x  =(const float*)d_in[0];
    const float* buf=(const float*)d_in[1];
    const void*  msk=d_in[2];
    const float* Wk =(const float*)d_in[3];
    const float* bk =(const float*)d_in[4];
    const float* Wv =(const float*)d_in[5];
    const float* bv =(const float*)d_in[6];
    float* outp=(float*)d_out;

    cudaFuncSetAttribute(proj_kernel, cudaFuncAttributeMaxDynamicSharedMemorySize, PROJ_SMEM_BYTES);
    cudaFuncSetAttribute(attn_kernel, cudaFuncAttributeMaxDynamicSharedMemorySize, ATTN_SMEM);

    proj_kernel<<<512, 256, PROJ_SMEM_BYTES>>>(x, buf, Wk, bk, Wv, bv);
    mask_detect_kernel<<<1, 256>>>((const uint32_t*)msk);
    mask_decode_kernel<<<NROWS/256, 256>>>(msk);
    attn_kernel<<<256, 256, ATTN_SMEM>>>(outp);
}